// round 16
// baseline (speedup 1.0000x reference)
#include <cuda_runtime.h>

// ProjectionSimToPointCloud: image (2048, 8192, 4) f32 -> points (2048*8192, 3) f32
//   depth = image[..., 3]
//   pitch(i) = (1 - i/h) * (FOV_UP + |FOV_DOWN|) - |FOV_DOWN|
//   yaw(j)   = j/w * 2*pi - pi
//   x = depth*cos(yaw), y = -depth*sin(yaw), z = depth*sin(pitch)
//
// R15 confirmed the CTA-granularity gradient: block 256->128 gave
// 68.6->67.8us kernel, DRAM 78.3%. This round steps once more along it:
// block 128 -> 64 (65536 CTAs, 2 warps/CTA). regs=24 -> occupancy still
// full (32 CTAs/SM x 64 = 2048 thr/SM).
//  - 4x fully-coalesced LDG.128 front-batched (MLP=4)
//  - 3x STG.128 contiguous per thread
//  - inline MUFU trig, hidden under the DRAM-bound window
// Falsified: scalar loads, PPT=8, __ldcs/__stcs, L2::256B, persistent
// grid, trig-table prekernel. DRAM ~78% = mixed R/W controller ceiling.

#define IMG_H 2048
#define IMG_W 8192
#define PPT   4     // pixels per thread
#define BLOCK 64

__global__ void __launch_bounds__(BLOCK) project_fused_v4(
    const float4* __restrict__ img,   // (H*W) float4 pixels, .w = depth
    float* __restrict__ out)          // (H*W*3) floats
{
    const int t  = blockIdx.x * blockDim.x + threadIdx.x;
    const int p0 = t * PPT;                     // first pixel (multiple of 4)
    const int j0 = p0 & (IMG_W - 1);            // row not crossed (W % 4 == 0)
    const int i  = p0 >> 13;                    // log2(IMG_W) = 13

    // 4 independent fully-coalesced 128-bit loads, front-batched (MLP=4).
    const float4 v0 = img[p0 + 0];
    const float4 v1 = img[p0 + 1];
    const float4 v2 = img[p0 + 2];
    const float4 v3 = img[p0 + 3];
    const float d0 = v0.w, d1 = v1.w, d2 = v2.w, d3 = v3.w;

    // yaw(j) = j * (2*pi/W) - pi
    const float YAW_STEP = 7.6699039394282161e-4f;   // 2*pi/8192
    const float PI_F     = 3.14159265358979323846f;
    const float yaw0 = (float)j0 * YAW_STEP - PI_F;

    float s0, c0, s1, c1, s2, c2, s3, c3;
    __sincosf(yaw0,                  &s0, &c0);
    __sincosf(yaw0 + 1.f * YAW_STEP, &s1, &c1);
    __sincosf(yaw0 + 2.f * YAW_STEP, &s2, &c2);
    __sincosf(yaw0 + 3.f * YAW_STEP, &s3, &c3);

    // pitch(i) = FOV_UP - i * (span/H); warp-uniform.
    const float PITCH_A = 0.26179938779914943654f;   // FOV_UP in radians
    const float PITCH_B = 2.5566346454293863e-4f;    // (30deg in rad)/2048
    const float sp = __sinf(PITCH_A - (float)i * PITCH_B);

    // 12 output floats = 48 contiguous bytes, 16B-aligned -> 3x STG.128.
    float4 o0, o1, o2;
    o0.x = d0 * c0;   o0.y = -d0 * s0;  o0.z = d0 * sp;
    o0.w = d1 * c1;
    o1.x = -d1 * s1;  o1.y = d1 * sp;
    o1.z = d2 * c2;   o1.w = -d2 * s2;
    o2.x = d2 * sp;
    o2.y = d3 * c3;   o2.z = -d3 * s3;  o2.w = d3 * sp;

    float4* outv = reinterpret_cast<float4*>(out) + t * 3;
    outv[0] = o0;
    outv[1] = o1;
    outv[2] = o2;
}

extern "C" void kernel_launch(void* const* d_in, const int* in_sizes, int n_in,
                              void* d_out, int out_size) {
    const float4* img = (const float4*)d_in[0];
    float* out = (float*)d_out;

    const int n_threads = (IMG_H * IMG_W) / PPT;   // 4,194,304
    project_fused_v4<<<n_threads / BLOCK, BLOCK>>>(img, out);
}